// round 12
// baseline (speedup 1.0000x reference)
#include <cuda_runtime.h>

#define LAYERS 12
#define NROW   4096
#define DD     16
#define TPB    256
#define QPT    8                                   // quarter-rows per thread
#define NBLK   96                                  // 8 blocks per layer
#define NWARP  (TPB / 32)
#define FULL   0xffffffffu

// Per-layer accumulators, padded to 36 floats (144B, 16B-aligned).
// Slots: [0..15]=sum p, [16..31]=sum log_q, [32]=sum diag.
// Zeroed at module load; finalize re-zeroes after use (deterministic replays).
__device__ __align__(16) float g_acc[LAYERS][36];

// ---------------------------------------------------------------------------
// Kernel 1: per-layer sums. Key trick: NO log in the row loop — accumulate
// the PRODUCT of row softmax-denominators and take one log at the end:
//   sum_rows log(s) = log(prod_rows s)      (s in [~6,~70], 8 rows: no overflow)
//   sum_rows log_q[d] = sum_rows v[d] - sum_rows log(s)
//   sum_rows diag     = sum_rows (t/s)     - sum_rows log(s)   (since sum_d p = 1)
// ---------------------------------------------------------------------------
__global__ void __launch_bounds__(TPB) accum_kernel(const float* __restrict__ x) {
    const int tid   = threadIdx.x;
    const int lane  = tid & 31;
    const int wid   = tid >> 5;
    const int layer = blockIdx.x >> 3;              // 8 blocks/layer, uniform

    // 8 quarter-rows from 8 independent rows; 4 consecutive lanes = one row.
    const int qbase = blockIdx.x * (TPB * QPT) + tid;
    float4 a[QPT];
#pragma unroll
    for (int k = 0; k < QPT; k++)
        a[k] = reinterpret_cast<const float4*>(x)[qbase + k * TPB];

    // No max-subtract: inputs are N(0,1); exp() cannot overflow fp32.
    float r[8];                 // [0..3] = sum_k p[d], [4..7] = sum_k v[d]
    float diag = 0.f;           // lane-local sum of inv*t  (p·v partials)
    float prod = 1.f;           // product of row sums s (group-uniform)
#pragma unroll
    for (int i = 0; i < 4; i++) r[i] = r[i + 4] = 0.f;

#pragma unroll
    for (int k = 0; k < QPT; k++) {
        float v[4] = { a[k].x, a[k].y, a[k].z, a[k].w };
        float e[4];
        float u = 0.f, t = 0.f;
#pragma unroll
        for (int i = 0; i < 4; i++) {
            e[i] = __expf(v[i]);
            u += e[i];
            t = fmaf(e[i], v[i], t);            // lane-local sum e*v
        }
        float s = u;                             // row sum across 4 lanes
        s += __shfl_xor_sync(FULL, s, 1);
        s += __shfl_xor_sync(FULL, s, 2);
        const float inv = 1.0f / s;

        prod *= s;                               // defer the log
        diag  = fmaf(inv, t, diag);              // sum_d(p*v) partial

#pragma unroll
        for (int i = 0; i < 4; i++) {
            r[i]     = fmaf(e[i], inv, r[i]);    // p accumulation
            r[i + 4] += v[i];                     // raw logit accumulation
        }
    }

    // One log per thread, off the loop's dependent chain.
    const float lgt = __logf(prod);              // sum over this group's 8 rows of log(s)

    // Fold the deferred log into the v-sums (each dim appears once per row).
#pragma unroll
    for (int i = 0; i < 4; i++) r[i + 4] -= lgt;

    // diag: complete within the 4-lane group, then subtract the group's log-sum.
    diag += __shfl_xor_sync(FULL, diag, 1);
    diag += __shfl_xor_sync(FULL, diag, 2);
    diag -= lgt;                                 // group-uniform now
    // sum across the 8 groups
#pragma unroll
    for (int off = 4; off <= 16; off <<= 1)
        diag += __shfl_xor_sync(FULL, diag, off);

    // ---- recursive-halving warp reduce of r: masks {4,8,16} (7 SHFLs) ----
    float t4[4];
    {
        const bool up = (lane & 4) != 0;
#pragma unroll
        for (int i = 0; i < 4; i++) {
            float snd  = up ? r[i] : r[i + 4];
            float recv = __shfl_xor_sync(FULL, snd, 4);
            t4[i] = (up ? r[i + 4] : r[i]) + recv;
        }
    }
    float t2[2];
    {
        const bool up = (lane & 8) != 0;
#pragma unroll
        for (int i = 0; i < 2; i++) {
            float snd  = up ? t4[i] : t4[i + 2];
            float recv = __shfl_xor_sync(FULL, snd, 8);
            t2[i] = (up ? t4[i + 2] : t4[i]) + recv;
        }
    }
    float t1;
    {
        const bool up = (lane & 16) != 0;
        float snd  = up ? t2[0] : t2[1];
        float recv = __shfl_xor_sync(FULL, snd, 16);
        t1 = (up ? t2[1] : t2[0]) + recv;
    }

    // lane -> sum slot for t1
    const int istar = (((lane >> 2) & 1) << 2) | (((lane >> 3) & 1) << 1) | ((lane >> 4) & 1);
    const int S     = ((istar & 4) ? DD : 0) + (lane & 3) * 4 + (istar & 3);

    __shared__ float smem[NWARP][34];
    smem[wid][S] = t1;
    if (lane == 0) smem[wid][32] = diag;
    __syncthreads();

    if (tid < 33) {
        float acc = 0.f;
#pragma unroll
        for (int w = 0; w < NWARP; w++) acc += smem[w][tid];
        atomicAdd(&g_acc[layer][tid], acc);      // REDG (no return)
    }
}

// ---------------------------------------------------------------------------
// Kernel 2: finalize, PDL. One warp per layer, lanes parallel over d.
// ---------------------------------------------------------------------------
__global__ void __launch_bounds__(384) finalize_kernel(float* __restrict__ out) {
    asm volatile("griddepcontrol.wait;" ::: "memory");

    const int tid  = threadIdx.x;
    const int w    = tid >> 5;       // warp = layer (w < 12)
    const int lane = tid & 31;

    __shared__ float s_a1[LAYERS], s_a2[LAYERS];

    if (w < LAYERS) {
        float sp   = (lane < DD) ? __ldcg(&g_acc[w][lane])      : 0.f;
        float slq  = (lane < DD) ? __ldcg(&g_acc[w][DD + lane]) : 0.f;
        float diag = __ldcg(&g_acc[w][32]);

        float dot = sp * slq;
        float spt = sp;
#pragma unroll
        for (int off = 16; off > 0; off >>= 1) {
            dot += __shfl_xor_sync(FULL, dot, off);
            spt += __shfl_xor_sync(FULL, spt, off);
        }
        const float invt = 1.0f / spt;
        float ls = (lane < DD) ? __logf(sp * invt + 1e-8f) : 0.f;
#pragma unroll
        for (int off = 16; off > 0; off >>= 1)
            ls += __shfl_xor_sync(FULL, ls, off);

        if (lane == 0) {
            s_a1[w] = dot - diag;
            s_a2[w] = -ls / (float)DD;
        }
    }
    __syncthreads();

    if (tid < 32) {
        float a1 = (lane < LAYERS) ? s_a1[lane] : 0.f;
        float a2 = (lane < LAYERS) ? s_a2[lane] : 0.f;
#pragma unroll
        for (int off = 16; off > 0; off >>= 1) {
            a1 += __shfl_xor_sync(FULL, a1, off);
            a2 += __shfl_xor_sync(FULL, a2, off);
        }
        if (lane == 0) {
            const float aux1 = a1 / (2.0f * (float)LAYERS);
            const float aux2 = a2 / (float)LAYERS;
            out[0] = 0.01f * (aux1 + aux2);      // ALPHA*(BETA*aux1 + aux2)
        }
    }

    // Re-zero accumulators for the next replay.
    if (tid < LAYERS * 36 / 4) {
        float4* gz = reinterpret_cast<float4*>(&g_acc[0][0]);
        gz[tid] = make_float4(0.f, 0.f, 0.f, 0.f);
    }
}

extern "C" void kernel_launch(void* const* d_in, const int* in_sizes, int n_in,
                              void* d_out, int out_size) {
    const float* x = (const float*)d_in[0];
    float* out = (float*)d_out;

    accum_kernel<<<NBLK, TPB>>>(x);

    cudaLaunchConfig_t cfg = {};
    cfg.gridDim  = dim3(1, 1, 1);
    cfg.blockDim = dim3(384, 1, 1);
    cfg.dynamicSmemBytes = 0;
    cfg.stream = 0;
    cudaLaunchAttribute attr[1];
    attr[0].id = cudaLaunchAttributeProgrammaticStreamSerialization;
    attr[0].val.programmaticStreamSerializationAllowed = 1;
    cfg.attrs = attr;
    cfg.numAttrs = 1;
    cudaLaunchKernelEx(&cfg, finalize_kernel, out);
}

// round 13
// speedup vs baseline: 1.0294x; 1.0294x over previous
#include <cuda_runtime.h>

#define LAYERS 12
#define NROW   4096
#define DD     16
#define TPB    256
#define QPT    4                                   // quarter-rows per thread
#define NBLK   192                                 // 16 blocks per layer
#define NWARP  (TPB / 32)
#define FULL   0xffffffffu

// Per-layer accumulators, padded to 36 floats (144B, 16B-aligned).
// Slots: [0..15]=sum p, [16..31]=sum log_q, [32]=sum diag.
// Zeroed at module load; finalize re-zeroes after use (deterministic replays).
__device__ __align__(16) float g_acc[LAYERS][36];

// ---------------------------------------------------------------------------
// Kernel 1: per-layer sums. Deferred-log accum body (one __logf per thread:
//   sum_rows log(s) = log(prod_rows s), prod of 4 row-sums <= ~2.4e7, safe).
// After the block's atomics land, fire the EXPLICIT PDL trigger so finalize's
// griddepcontrol.wait releases at trigger-pass time instead of grid teardown.
// ---------------------------------------------------------------------------
__global__ void __launch_bounds__(TPB) accum_kernel(const float* __restrict__ x) {
    const int tid   = threadIdx.x;
    const int lane  = tid & 31;
    const int wid   = tid >> 5;
    const int layer = blockIdx.x >> 4;              // 16 blocks/layer, uniform

    // 4 quarter-rows from 4 independent rows; 4 consecutive lanes = one row.
    const int qbase = blockIdx.x * (TPB * QPT) + tid;
    float4 a[QPT];
#pragma unroll
    for (int k = 0; k < QPT; k++)
        a[k] = reinterpret_cast<const float4*>(x)[qbase + k * TPB];

    // No max-subtract: inputs are N(0,1); exp() cannot overflow fp32.
    float r[8];                 // [0..3] = sum_k p[d], [4..7] = sum_k v[d]
    float diag = 0.f;           // lane-local sum of inv*t (p·v partials)
    float prod = 1.f;           // product of row sums s (group-uniform)
#pragma unroll
    for (int i = 0; i < 4; i++) r[i] = r[i + 4] = 0.f;

#pragma unroll
    for (int k = 0; k < QPT; k++) {
        float v[4] = { a[k].x, a[k].y, a[k].z, a[k].w };
        float e[4];
        float u = 0.f, t = 0.f;
#pragma unroll
        for (int i = 0; i < 4; i++) {
            e[i] = __expf(v[i]);
            u += e[i];
            t = fmaf(e[i], v[i], t);            // lane-local sum e*v
        }
        float s = u;                             // row sum across 4 lanes
        s += __shfl_xor_sync(FULL, s, 1);
        s += __shfl_xor_sync(FULL, s, 2);
        const float inv = 1.0f / s;

        prod *= s;                               // defer the log
        diag  = fmaf(inv, t, diag);              // sum_d(p*v) partial

#pragma unroll
        for (int i = 0; i < 4; i++) {
            r[i]     = fmaf(e[i], inv, r[i]);    // p accumulation
            r[i + 4] += v[i];                     // raw logit accumulation
        }
    }

    // One log per thread, off the loop's dependent chain.
    const float lgt = __logf(prod);              // sum of log(s) over this group's 4 rows
#pragma unroll
    for (int i = 0; i < 4; i++) r[i + 4] -= lgt; // fold into log_q sums

    // diag: finish within the 4-lane group, subtract group's log-sum, then
    // sum across the 8 groups (group-uniform → masks 4,8,16 suffice).
    diag += __shfl_xor_sync(FULL, diag, 1);
    diag += __shfl_xor_sync(FULL, diag, 2);
    diag -= lgt;
#pragma unroll
    for (int off = 4; off <= 16; off <<= 1)
        diag += __shfl_xor_sync(FULL, diag, off);

    // ---- recursive-halving warp reduce of r: masks {4,8,16} (7 SHFLs) ----
    float t4[4];
    {
        const bool up = (lane & 4) != 0;
#pragma unroll
        for (int i = 0; i < 4; i++) {
            float snd  = up ? r[i] : r[i + 4];
            float recv = __shfl_xor_sync(FULL, snd, 4);
            t4[i] = (up ? r[i + 4] : r[i]) + recv;
        }
    }
    float t2[2];
    {
        const bool up = (lane & 8) != 0;
#pragma unroll
        for (int i = 0; i < 2; i++) {
            float snd  = up ? t4[i] : t4[i + 2];
            float recv = __shfl_xor_sync(FULL, snd, 8);
            t2[i] = (up ? t4[i + 2] : t4[i]) + recv;
        }
    }
    float t1;
    {
        const bool up = (lane & 16) != 0;
        float snd  = up ? t2[0] : t2[1];
        float recv = __shfl_xor_sync(FULL, snd, 16);
        t1 = (up ? t2[1] : t2[0]) + recv;
    }

    // lane -> sum slot for t1
    const int istar = (((lane >> 2) & 1) << 2) | (((lane >> 3) & 1) << 1) | ((lane >> 4) & 1);
    const int S     = ((istar & 4) ? DD : 0) + (lane & 3) * 4 + (istar & 3);

    __shared__ float smem[NWARP][34];
    smem[wid][S] = t1;
    if (lane == 0) smem[wid][32] = diag;
    __syncthreads();

    if (tid < 33) {
        float acc = 0.f;
#pragma unroll
        for (int w = 0; w < NWARP; w++) acc += smem[w][tid];
        atomicAdd(&g_acc[layer][tid], acc);      // REDG (no return)
    }
    __syncthreads();   // block's atomics are program-ordered before the trigger

    // Explicit early PDL trigger: finalize's wait releases once every block
    // has passed this point (pre-trigger memory ops visible), skipping
    // grid-teardown latency.
    asm volatile("griddepcontrol.launch_dependents;" ::: "memory");
}

// ---------------------------------------------------------------------------
// Kernel 2: finalize, PDL. One warp per layer, lanes parallel over d.
// ---------------------------------------------------------------------------
__global__ void __launch_bounds__(384) finalize_kernel(float* __restrict__ out) {
    asm volatile("griddepcontrol.wait;" ::: "memory");

    const int tid  = threadIdx.x;
    const int w    = tid >> 5;       // warp = layer (w < 12)
    const int lane = tid & 31;

    __shared__ float s_a1[LAYERS], s_a2[LAYERS];

    if (w < LAYERS) {
        float sp   = (lane < DD) ? __ldcg(&g_acc[w][lane])      : 0.f;
        float slq  = (lane < DD) ? __ldcg(&g_acc[w][DD + lane]) : 0.f;
        float diag = __ldcg(&g_acc[w][32]);

        float dot = sp * slq;
        float spt = sp;
#pragma unroll
        for (int off = 16; off > 0; off >>= 1) {
            dot += __shfl_xor_sync(FULL, dot, off);
            spt += __shfl_xor_sync(FULL, spt, off);
        }
        const float invt = 1.0f / spt;
        float ls = (lane < DD) ? __logf(sp * invt + 1e-8f) : 0.f;
#pragma unroll
        for (int off = 16; off > 0; off >>= 1)
            ls += __shfl_xor_sync(FULL, ls, off);

        if (lane == 0) {
            s_a1[w] = dot - diag;
            s_a2[w] = -ls / (float)DD;
        }
    }
    __syncthreads();

    if (tid < 32) {
        float a1 = (lane < LAYERS) ? s_a1[lane] : 0.f;
        float a2 = (lane < LAYERS) ? s_a2[lane] : 0.f;
#pragma unroll
        for (int off = 16; off > 0; off >>= 1) {
            a1 += __shfl_xor_sync(FULL, a1, off);
            a2 += __shfl_xor_sync(FULL, a2, off);
        }
        if (lane == 0) {
            const float aux1 = a1 / (2.0f * (float)LAYERS);
            const float aux2 = a2 / (float)LAYERS;
            out[0] = 0.01f * (aux1 + aux2);      // ALPHA*(BETA*aux1 + aux2)
        }
    }

    // Re-zero accumulators for the next replay.
    if (tid < LAYERS * 36 / 4) {
        float4* gz = reinterpret_cast<float4*>(&g_acc[0][0]);
        gz[tid] = make_float4(0.f, 0.f, 0.f, 0.f);
    }
}

extern "C" void kernel_launch(void* const* d_in, const int* in_sizes, int n_in,
                              void* d_out, int out_size) {
    const float* x = (const float*)d_in[0];
    float* out = (float*)d_out;

    accum_kernel<<<NBLK, TPB>>>(x);

    cudaLaunchConfig_t cfg = {};
    cfg.gridDim  = dim3(1, 1, 1);
    cfg.blockDim = dim3(384, 1, 1);
    cfg.dynamicSmemBytes = 0;
    cfg.stream = 0;
    cudaLaunchAttribute attr[1];
    attr[0].id = cudaLaunchAttributeProgrammaticStreamSerialization;
    attr[0].val.programmaticStreamSerializationAllowed = 1;
    cfg.attrs = attr;
    cfg.numAttrs = 1;
    cudaLaunchKernelEx(&cfg, finalize_kernel, out);
}

// round 14
// speedup vs baseline: 1.0332x; 1.0037x over previous
#include <cuda_runtime.h>

#define LAYERS 12
#define NROW   4096
#define DD     16
#define TPB    256
#define QPT    4                                   // quarter-rows per thread
#define NBLK   192                                 // 16 blocks per layer
#define NWARP  (TPB / 32)
#define FULL   0xffffffffu

// Per-layer accumulators, padded to 36 floats (144B, 16B-aligned).
// Slots: [0..15]=sum p, [16..31]=sum log_q, [32]=sum diag.
// Zeroed at module load; finalize re-zeroes after use (deterministic replays).
__device__ __align__(16) float g_acc[LAYERS][36];

// ---------------------------------------------------------------------------
// Kernel 1: per-layer sums. Deferred-log body (one __logf per thread).
// NO smem / NO __syncthreads: each warp fires its 33 spread-address REDG
// atomics directly, then hits the explicit PDL trigger — the shortest
// possible path from launch to "finalize may proceed".
// ---------------------------------------------------------------------------
__global__ void __launch_bounds__(TPB) accum_kernel(const float* __restrict__ x) {
    const int tid   = threadIdx.x;
    const int lane  = tid & 31;
    const int layer = blockIdx.x >> 4;              // 16 blocks/layer, uniform

    // 4 quarter-rows from 4 independent rows; 4 consecutive lanes = one row.
    const int qbase = blockIdx.x * (TPB * QPT) + tid;
    float4 a[QPT];
#pragma unroll
    for (int k = 0; k < QPT; k++)
        a[k] = reinterpret_cast<const float4*>(x)[qbase + k * TPB];

    // No max-subtract: inputs are N(0,1); exp() cannot overflow fp32.
    float r[8];                 // [0..3] = sum_k p[d], [4..7] = sum_k v[d]
    float diag = 0.f;           // lane-local sum of inv*t (p·v partials)
    float prod = 1.f;           // product of row sums s (group-uniform)
#pragma unroll
    for (int i = 0; i < 4; i++) r[i] = r[i + 4] = 0.f;

#pragma unroll
    for (int k = 0; k < QPT; k++) {
        float v[4] = { a[k].x, a[k].y, a[k].z, a[k].w };
        float e[4];
        float u = 0.f, t = 0.f;
#pragma unroll
        for (int i = 0; i < 4; i++) {
            e[i] = __expf(v[i]);
            u += e[i];
            t = fmaf(e[i], v[i], t);            // lane-local sum e*v
        }
        float s = u;                             // row sum across 4 lanes
        s += __shfl_xor_sync(FULL, s, 1);
        s += __shfl_xor_sync(FULL, s, 2);
        const float inv = 1.0f / s;

        prod *= s;                               // defer the log
        diag  = fmaf(inv, t, diag);              // sum_d(p*v) partial

#pragma unroll
        for (int i = 0; i < 4; i++) {
            r[i]     = fmaf(e[i], inv, r[i]);    // p accumulation
            r[i + 4] += v[i];                     // raw logit accumulation
        }
    }

    // One log per thread, off the loop's dependent chain.
    const float lgt = __logf(prod);              // sum of log(s) over the group's 4 rows
#pragma unroll
    for (int i = 0; i < 4; i++) r[i + 4] -= lgt; // fold into log_q sums

    // diag: finish within the 4-lane group, subtract group log-sum, then
    // sum across the 8 groups (group-uniform → masks 4,8,16).
    diag += __shfl_xor_sync(FULL, diag, 1);
    diag += __shfl_xor_sync(FULL, diag, 2);
    diag -= lgt;
#pragma unroll
    for (int off = 4; off <= 16; off <<= 1)
        diag += __shfl_xor_sync(FULL, diag, off);

    // ---- recursive-halving warp reduce of r: masks {4,8,16} (7 SHFLs) ----
    float t4[4];
    {
        const bool up = (lane & 4) != 0;
#pragma unroll
        for (int i = 0; i < 4; i++) {
            float snd  = up ? r[i] : r[i + 4];
            float recv = __shfl_xor_sync(FULL, snd, 4);
            t4[i] = (up ? r[i + 4] : r[i]) + recv;
        }
    }
    float t2[2];
    {
        const bool up = (lane & 8) != 0;
#pragma unroll
        for (int i = 0; i < 2; i++) {
            float snd  = up ? t4[i] : t4[i + 2];
            float recv = __shfl_xor_sync(FULL, snd, 8);
            t2[i] = (up ? t4[i + 2] : t4[i]) + recv;
        }
    }
    float t1;
    {
        const bool up = (lane & 16) != 0;
        float snd  = up ? t2[0] : t2[1];
        float recv = __shfl_xor_sync(FULL, snd, 16);
        t1 = (up ? t2[1] : t2[0]) + recv;
    }

    // lane -> sum slot for t1
    const int istar = (((lane >> 2) & 1) << 2) | (((lane >> 3) & 1) << 1) | ((lane >> 4) & 1);
    const int S     = ((istar & 4) ? DD : 0) + (lane & 3) * 4 + (istar & 3);

    // Per-warp direct REDG atomics: 32 spread addresses + diag from lane 0.
    // No smem phase, no block barrier before the trigger.
    atomicAdd(&g_acc[layer][S], t1);
    if (lane == 0) atomicAdd(&g_acc[layer][32], diag);

    // Explicit early PDL trigger: finalize's wait releases once every block
    // passes here; the atomics above are program-ordered before the trigger.
    asm volatile("griddepcontrol.launch_dependents;" ::: "memory");
}

// ---------------------------------------------------------------------------
// Kernel 2: finalize, PDL. One warp per layer, lanes parallel over d.
// ---------------------------------------------------------------------------
__global__ void __launch_bounds__(384) finalize_kernel(float* __restrict__ out) {
    asm volatile("griddepcontrol.wait;" ::: "memory");

    const int tid  = threadIdx.x;
    const int w    = tid >> 5;       // warp = layer (w < 12)
    const int lane = tid & 31;

    __shared__ float s_a1[LAYERS], s_a2[LAYERS];

    if (w < LAYERS) {
        float sp   = (lane < DD) ? __ldcg(&g_acc[w][lane])      : 0.f;
        float slq  = (lane < DD) ? __ldcg(&g_acc[w][DD + lane]) : 0.f;
        float diag = __ldcg(&g_acc[w][32]);

        float dot = sp * slq;
        float spt = sp;
#pragma unroll
        for (int off = 16; off > 0; off >>= 1) {
            dot += __shfl_xor_sync(FULL, dot, off);
            spt += __shfl_xor_sync(FULL, spt, off);
        }
        const float invt = 1.0f / spt;
        float ls = (lane < DD) ? __logf(sp * invt + 1e-8f) : 0.f;
#pragma unroll
        for (int off = 16; off > 0; off >>= 1)
            ls += __shfl_xor_sync(FULL, ls, off);

        if (lane == 0) {
            s_a1[w] = dot - diag;
            s_a2[w] = -ls / (float)DD;
        }
    }
    __syncthreads();

    if (tid < 32) {
        float a1 = (lane < LAYERS) ? s_a1[lane] : 0.f;
        float a2 = (lane < LAYERS) ? s_a2[lane] : 0.f;
#pragma unroll
        for (int off = 16; off > 0; off >>= 1) {
            a1 += __shfl_xor_sync(FULL, a1, off);
            a2 += __shfl_xor_sync(FULL, a2, off);
        }
        if (lane == 0) {
            const float aux1 = a1 / (2.0f * (float)LAYERS);
            const float aux2 = a2 / (float)LAYERS;
            out[0] = 0.01f * (aux1 + aux2);      // ALPHA*(BETA*aux1 + aux2)
        }
    }

    // Re-zero accumulators for the next replay.
    if (tid < LAYERS * 36 / 4) {
        float4* gz = reinterpret_cast<float4*>(&g_acc[0][0]);
        gz[tid] = make_float4(0.f, 0.f, 0.f, 0.f);
    }
}

extern "C" void kernel_launch(void* const* d_in, const int* in_sizes, int n_in,
                              void* d_out, int out_size) {
    const float* x = (const float*)d_in[0];
    float* out = (float*)d_out;

    accum_kernel<<<NBLK, TPB>>>(x);

    cudaLaunchConfig_t cfg = {};
    cfg.gridDim  = dim3(1, 1, 1);
    cfg.blockDim = dim3(384, 1, 1);
    cfg.dynamicSmemBytes = 0;
    cfg.stream = 0;
    cudaLaunchAttribute attr[1];
    attr[0].id = cudaLaunchAttributeProgrammaticStreamSerialization;
    attr[0].val.programmaticStreamSerializationAllowed = 1;
    cfg.attrs = attr;
    cfg.numAttrs = 1;
    cudaLaunchKernelEx(&cfg, finalize_kernel, out);
}

// round 16
// speedup vs baseline: 1.0370x; 1.0037x over previous
#include <cuda_runtime.h>

#define LAYERS 12
#define NROW   4096
#define DD     16
#define TPB    256
#define QPT    4                                   // quarter-rows per thread
#define NBLK   192                                 // 16 blocks per layer
#define NWARP  (TPB / 32)
#define FULL   0xffffffffu

// Per-layer accumulators, padded to 36 floats (144B, 16B-aligned).
// Slots: [0..15]=sum p, [16..31]=sum log_q, [32]=sum diag.
// Zeroed at module load; finalize re-zeroes after use (deterministic replays).
__device__ __align__(16) float g_acc[LAYERS][36];

// ---------------------------------------------------------------------------
// Kernel 1: per-layer sums. Deferred-log body (one __logf per thread).
// NO smem / NO __syncthreads: each warp fires its 33 spread-address REDG
// atomics directly, then hits the explicit PDL trigger — the shortest
// possible path from launch to "finalize may proceed".
// ---------------------------------------------------------------------------
__global__ void __launch_bounds__(TPB) accum_kernel(const float* __restrict__ x) {
    const int tid   = threadIdx.x;
    const int lane  = tid & 31;
    const int layer = blockIdx.x >> 4;              // 16 blocks/layer, uniform

    // 4 quarter-rows from 4 independent rows; 4 consecutive lanes = one row.
    const int qbase = blockIdx.x * (TPB * QPT) + tid;
    float4 a[QPT];
#pragma unroll
    for (int k = 0; k < QPT; k++)
        a[k] = reinterpret_cast<const float4*>(x)[qbase + k * TPB];

    // No max-subtract: inputs are N(0,1); exp() cannot overflow fp32.
    float r[8];                 // [0..3] = sum_k p[d], [4..7] = sum_k v[d]
    float diag = 0.f;           // lane-local sum of inv*t (p·v partials)
    float prod = 1.f;           // product of row sums s (group-uniform)
#pragma unroll
    for (int i = 0; i < 4; i++) r[i] = r[i + 4] = 0.f;

#pragma unroll
    for (int k = 0; k < QPT; k++) {
        float v[4] = { a[k].x, a[k].y, a[k].z, a[k].w };
        float e[4];
        float u = 0.f, t = 0.f;
#pragma unroll
        for (int i = 0; i < 4; i++) {
            e[i] = __expf(v[i]);
            u += e[i];
            t = fmaf(e[i], v[i], t);            // lane-local sum e*v
        }
        float s = u;                             // row sum across 4 lanes
        s += __shfl_xor_sync(FULL, s, 1);
        s += __shfl_xor_sync(FULL, s, 2);
        const float inv = 1.0f / s;

        prod *= s;                               // defer the log
        diag  = fmaf(inv, t, diag);              // sum_d(p*v) partial

#pragma unroll
        for (int i = 0; i < 4; i++) {
            r[i]     = fmaf(e[i], inv, r[i]);    // p accumulation
            r[i + 4] += v[i];                     // raw logit accumulation
        }
    }

    // One log per thread, off the loop's dependent chain.
    const float lgt = __logf(prod);              // sum of log(s) over the group's 4 rows
#pragma unroll
    for (int i = 0; i < 4; i++) r[i + 4] -= lgt; // fold into log_q sums

    // diag: finish within the 4-lane group, subtract group log-sum, then
    // sum across the 8 groups (group-uniform → masks 4,8,16).
    diag += __shfl_xor_sync(FULL, diag, 1);
    diag += __shfl_xor_sync(FULL, diag, 2);
    diag -= lgt;
#pragma unroll
    for (int off = 4; off <= 16; off <<= 1)
        diag += __shfl_xor_sync(FULL, diag, off);

    // ---- recursive-halving warp reduce of r: masks {4,8,16} (7 SHFLs) ----
    float t4[4];
    {
        const bool up = (lane & 4) != 0;
#pragma unroll
        for (int i = 0; i < 4; i++) {
            float snd  = up ? r[i] : r[i + 4];
            float recv = __shfl_xor_sync(FULL, snd, 4);
            t4[i] = (up ? r[i + 4] : r[i]) + recv;
        }
    }
    float t2[2];
    {
        const bool up = (lane & 8) != 0;
#pragma unroll
        for (int i = 0; i < 2; i++) {
            float snd  = up ? t4[i] : t4[i + 2];
            float recv = __shfl_xor_sync(FULL, snd, 8);
            t2[i] = (up ? t4[i + 2] : t4[i]) + recv;
        }
    }
    float t1;
    {
        const bool up = (lane & 16) != 0;
        float snd  = up ? t2[0] : t2[1];
        float recv = __shfl_xor_sync(FULL, snd, 16);
        t1 = (up ? t2[1] : t2[0]) + recv;
    }

    // lane -> sum slot for t1
    const int istar = (((lane >> 2) & 1) << 2) | (((lane >> 3) & 1) << 1) | ((lane >> 4) & 1);
    const int S     = ((istar & 4) ? DD : 0) + (lane & 3) * 4 + (istar & 3);

    // Per-warp direct REDG atomics: 32 spread addresses + diag from lane 0.
    // No smem phase, no block barrier before the trigger.
    atomicAdd(&g_acc[layer][S], t1);
    if (lane == 0) atomicAdd(&g_acc[layer][32], diag);

    // Explicit early PDL trigger: finalize's wait releases once every block
    // passes here; the atomics above are program-ordered before the trigger.
    asm volatile("griddepcontrol.launch_dependents;" ::: "memory");
}

// ---------------------------------------------------------------------------
// Kernel 2: finalize, PDL. One warp per layer, lanes parallel over d.
// ---------------------------------------------------------------------------
__global__ void __launch_bounds__(384) finalize_kernel(float* __restrict__ out) {
    asm volatile("griddepcontrol.wait;" ::: "memory");

    const int tid  = threadIdx.x;
    const int w    = tid >> 5;       // warp = layer (w < 12)
    const int lane = tid & 31;

    __shared__ float s_a1[LAYERS], s_a2[LAYERS];

    if (w < LAYERS) {
        float sp   = (lane < DD) ? __ldcg(&g_acc[w][lane])      : 0.f;
        float slq  = (lane < DD) ? __ldcg(&g_acc[w][DD + lane]) : 0.f;
        float diag = __ldcg(&g_acc[w][32]);

        float dot = sp * slq;
        float spt = sp;
#pragma unroll
        for (int off = 16; off > 0; off >>= 1) {
            dot += __shfl_xor_sync(FULL, dot, off);
            spt += __shfl_xor_sync(FULL, spt, off);
        }
        const float invt = 1.0f / spt;
        float ls = (lane < DD) ? __logf(sp * invt + 1e-8f) : 0.f;
#pragma unroll
        for (int off = 16; off > 0; off >>= 1)
            ls += __shfl_xor_sync(FULL, ls, off);

        if (lane == 0) {
            s_a1[w] = dot - diag;
            s_a2[w] = -ls / (float)DD;
        }
    }
    __syncthreads();

    if (tid < 32) {
        float a1 = (lane < LAYERS) ? s_a1[lane] : 0.f;
        float a2 = (lane < LAYERS) ? s_a2[lane] : 0.f;
#pragma unroll
        for (int off = 16; off > 0; off >>= 1) {
            a1 += __shfl_xor_sync(FULL, a1, off);
            a2 += __shfl_xor_sync(FULL, a2, off);
        }
        if (lane == 0) {
            const float aux1 = a1 / (2.0f * (float)LAYERS);
            const float aux2 = a2 / (float)LAYERS;
            out[0] = 0.01f * (aux1 + aux2);      // ALPHA*(BETA*aux1 + aux2)
        }
    }

    // Re-zero accumulators for the next replay.
    if (tid < LAYERS * 36 / 4) {
        float4* gz = reinterpret_cast<float4*>(&g_acc[0][0]);
        gz[tid] = make_float4(0.f, 0.f, 0.f, 0.f);
    }
}

extern "C" void kernel_launch(void* const* d_in, const int* in_sizes, int n_in,
                              void* d_out, int out_size) {
    const float* x = (const float*)d_in[0];
    float* out = (float*)d_out;

    accum_kernel<<<NBLK, TPB>>>(x);

    cudaLaunchConfig_t cfg = {};
    cfg.gridDim  = dim3(1, 1, 1);
    cfg.blockDim = dim3(384, 1, 1);
    cfg.dynamicSmemBytes = 0;
    cfg.stream = 0;
    cudaLaunchAttribute attr[1];
    attr[0].id = cudaLaunchAttributeProgrammaticStreamSerialization;
    attr[0].val.programmaticStreamSerializationAllowed = 1;
    cfg.attrs = attr;
    cfg.numAttrs = 1;
    cudaLaunchKernelEx(&cfg, finalize_kernel, out);
}